// round 14
// baseline (speedup 1.0000x reference)
#include <cuda_runtime.h>
#include <cuda_bf16.h>
#include <mma.h>
#include <math.h>
#include <stdint.h>

using namespace nvcuda;

#define N_NODES 50000
#define N_EDGES 800000
#define H 128
#define G_RBF 50
#define NBINS 7
#define CUTOFF 6.0f
#define SSP_SHIFT 0.6931471805599453f
#define PI_F 3.14159265358979323846f

#define SCAN_BLOCKS ((N_NODES + 255) / 256)   // 196
#define TILE_M 128
#define N_TILES ((N_NODES + TILE_M - 1) / TILE_M)   // 391
#define WL 136            // bf16 leading dim (128 + 8 pad)
#define OL 132            // f32 output leading dim (128 + 4 pad)
#define WIMG_U32 17408    // per-matrix packed image: hi(8704 u32) + lo(8704 u32)

// smem layout (bytes)
#define SM_AHI 0
#define SM_ALO (TILE_M * WL * 2)                 // 34816
#define SM_BHI (2 * TILE_M * WL * 2)             // 69632
#define SM_BLO (SM_BHI + H * WL * 2)             // 104448
#define TCG_SMEM (SM_BHI + 2 * H * WL * 2)       // 139264

// ---------------- scratch ----------------
__device__ float  g_v[N_NODES * H];
__device__ float  g_vlin[N_NODES * H];
__device__ float  g_agg[N_NODES * H];
__device__ float  g_wtab[2 * NBINS * H];
__device__ uint32_t g_wpk[7 * WIMG_U32];
__device__ int   g_cnt[N_NODES];
__device__ int   g_off[N_NODES + 1];
__device__ int   g_pos[N_NODES];
__device__ int   g_bsum[SCAN_BLOCKS];
__device__ int   g_jt[N_EDGES];
__device__ float g_cs[N_EDGES];

__device__ __forceinline__ float sspf(float x) {
    return fmaxf(x, 0.0f) + log1pf(expf(-fabsf(x))) - SSP_SHIFT;
}

__device__ __forceinline__ uint32_t pack_bf16x2(float x0, float x1) {
    __nv_bfloat16 h0 = __float2bfloat16_rn(x0);
    __nv_bfloat16 h1 = __float2bfloat16_rn(x1);
    return (uint32_t)__bfloat16_as_ushort(h0) |
           ((uint32_t)__bfloat16_as_ushort(h1) << 16);
}

// ---------------- W pre-split ----------------
__global__ void wsplit_kernel(const float* __restrict__ w0, const float* __restrict__ w1,
                              const float* __restrict__ w2, const float* __restrict__ w3,
                              const float* __restrict__ w4, const float* __restrict__ w5,
                              const float* __restrict__ w6, uint32_t* __restrict__ wpk) {
    const float* ws[7] = {w0, w1, w2, w3, w4, w5, w6};
    int m = blockIdx.y;
    const float* W = ws[m];
    int t = blockIdx.x * 256 + threadIdx.x;
    if (t >= 8192) return;
    int n = t & 127;
    int kp = t >> 7;
    float x0 = W[(2 * kp) * H + n];
    float x1 = W[(2 * kp + 1) * H + n];
    float h0 = __bfloat162float(__float2bfloat16_rn(x0));
    float h1 = __bfloat162float(__float2bfloat16_rn(x1));
    uint32_t* base = wpk + (size_t)m * WIMG_U32;
    base[(n * WL + 2 * kp) >> 1]          = pack_bf16x2(x0, x1);
    base[8704 + ((n * WL + 2 * kp) >> 1)] = pack_bf16x2(x0 - h0, x1 - h1);
}

// ================= shared building blocks =================
__device__ __forceinline__ void stage_B(char* sm, const uint32_t* wpk, int tid) {
    const float4* src = (const float4*)wpk;
    float4* dst = (float4*)(sm + SM_BHI);
    for (int i = tid; i < (2 * H * WL * 2) / 16; i += 512) dst[i] = src[i];
}

__device__ __forceinline__ void store_A4(char* sm, int node, int c, float4 a) {
    float hx = __bfloat162float(__float2bfloat16_rn(a.x));
    float hy = __bfloat162float(__float2bfloat16_rn(a.y));
    float hz = __bfloat162float(__float2bfloat16_rn(a.z));
    float hw = __bfloat162float(__float2bfloat16_rn(a.w));
    uint32_t boff = 2 * (node * WL + 4 * c);
    *(uint2*)(sm + SM_AHI + boff) = make_uint2(pack_bf16x2(a.x, a.y), pack_bf16x2(a.z, a.w));
    *(uint2*)(sm + SM_ALO + boff) = make_uint2(pack_bf16x2(a.x - hx, a.y - hy),
                                               pack_bf16x2(a.z - hz, a.w - hw));
}

// 3-term bf16-split MMA set; warp tile 32x32 -> acc[2][2]
// wrow = wid & 3 (32-row group), wcol = wid >> 2 (32-col group)
__device__ __forceinline__ void mma_set(const char* sm, int wid,
        wmma::fragment<wmma::accumulator, 16, 16, 16, float> acc[2][2]) {
    int wrow = wid & 3, wcol = wid >> 2;
    const __nv_bfloat16* Ahi = (const __nv_bfloat16*)(sm + SM_AHI) + wrow * 32 * WL;
    const __nv_bfloat16* Alo = (const __nv_bfloat16*)(sm + SM_ALO) + wrow * 32 * WL;
    const __nv_bfloat16* Bhi = (const __nv_bfloat16*)(sm + SM_BHI) + (wcol * 32) * WL;
    const __nv_bfloat16* Blo = (const __nv_bfloat16*)(sm + SM_BLO) + (wcol * 32) * WL;
#pragma unroll
    for (int r = 0; r < 2; r++)
#pragma unroll
        for (int c = 0; c < 2; c++) wmma::fill_fragment(acc[r][c], 0.0f);
#pragma unroll
    for (int ks = 0; ks < 8; ks++) {
        wmma::fragment<wmma::matrix_b, 16, 16, 16, __nv_bfloat16, wmma::col_major> bh[2], bl[2];
#pragma unroll
        for (int c = 0; c < 2; c++) {
            wmma::load_matrix_sync(bh[c], Bhi + (c * 16) * WL + ks * 16, WL);
            wmma::load_matrix_sync(bl[c], Blo + (c * 16) * WL + ks * 16, WL);
        }
#pragma unroll
        for (int r = 0; r < 2; r++) {
            wmma::fragment<wmma::matrix_a, 16, 16, 16, __nv_bfloat16, wmma::row_major> ah, al;
            wmma::load_matrix_sync(ah, Ahi + (r * 16) * WL + ks * 16, WL);
            wmma::load_matrix_sync(al, Alo + (r * 16) * WL + ks * 16, WL);
#pragma unroll
            for (int c = 0; c < 2; c++) {
                wmma::mma_sync(acc[r][c], ah, bh[c], acc[r][c]);
                wmma::mma_sync(acc[r][c], ah, bl[c], acc[r][c]);
                wmma::mma_sync(acc[r][c], al, bh[c], acc[r][c]);
            }
        }
    }
}

__device__ __forceinline__ void store_set(char* sm, int wid,
        wmma::fragment<wmma::accumulator, 16, 16, 16, float> acc[2][2]) {
    int wrow = wid & 3, wcol = wid >> 2;
    float* osm = (float*)(sm + SM_AHI);
#pragma unroll
    for (int r = 0; r < 2; r++)
#pragma unroll
        for (int c = 0; c < 2; c++)
            wmma::store_matrix_sync(osm + (wrow * 32 + r * 16) * OL + wcol * 32 + c * 16,
                                    acc[r][c], OL, wmma::mem_row_major);
}

// ---------------- gemm0_fused: v = z@iw+ib (written), vlin = v @ e_lin0 ----------------
__global__ void __launch_bounds__(512, 1) gemm0_fused(const float* __restrict__ z,
                                                      const float* __restrict__ iw,
                                                      const float* __restrict__ ib,
                                                      const uint32_t* __restrict__ wpk,
                                                      float* __restrict__ vout,
                                                      float* __restrict__ vlin, int n) {
    extern __shared__ char sm[];
    int tid = threadIdx.x;
    int nb = blockIdx.x * TILE_M;

    stage_B(sm, wpk, tid);
    for (int idx = tid; idx < TILE_M * 32; idx += 512) {
        int node = idx >> 5, c = idx & 31;
        int gn = nb + node;
        float4 val = make_float4(0.f, 0.f, 0.f, 0.f);
        if (gn < n) {
            float z0 = __ldg(z + gn * 3), z1 = __ldg(z + gn * 3 + 1), z2 = __ldg(z + gn * 3 + 2);
            float4 b  = __ldg((const float4*)ib + c);
            float4 w0 = __ldg((const float4*)iw + c);
            float4 w1 = __ldg((const float4*)iw + 32 + c);
            float4 w2 = __ldg((const float4*)iw + 64 + c);
            val.x = b.x + z0 * w0.x + z1 * w1.x + z2 * w2.x;
            val.y = b.y + z0 * w0.y + z1 * w1.y + z2 * w2.y;
            val.z = b.z + z0 * w0.z + z1 * w1.z + z2 * w2.z;
            val.w = b.w + z0 * w0.w + z1 * w1.w + z2 * w2.w;
            ((float4*)vout)[(size_t)gn * 32 + c] = val;
        }
        store_A4(sm, node, c, val);
    }
    __syncthreads();

    int wid = tid >> 5;
    wmma::fragment<wmma::accumulator, 16, 16, 16, float> acc[2][2];
    mma_set(sm, wid, acc);
    __syncthreads();
    store_set(sm, wid, acc);
    __syncthreads();

    // epilogue: thread -> (node = tid/4, 32-col group = (tid&3)*32)
    int node = tid >> 2, cb = (tid & 3) * 32;
    int gn = nb + node;
    if (gn < n) {
        const float* ip = (const float*)(sm + SM_AHI) + node * OL + cb;
        float4* op = (float4*)(vlin + (size_t)gn * H + cb);
#pragma unroll
        for (int i = 0; i < 8; i++)
            op[i] = make_float4(ip[4 * i], ip[4 * i + 1], ip[4 * i + 2], ip[4 * i + 3]);
    }
}

// ---------------- mlp_fused (layer 0): v += ssp(agg@W1+b1)@W2+b2 ; vlin = v@linW ----------------
__global__ void __launch_bounds__(512, 1) mlp_fused(const float* __restrict__ A,
                                                    const uint32_t* __restrict__ wpk1,
                                                    const float* __restrict__ b1,
                                                    const uint32_t* __restrict__ wpk2,
                                                    const float* __restrict__ b2,
                                                    float* __restrict__ v,
                                                    const uint32_t* __restrict__ wpkL,
                                                    float* __restrict__ vlin, int n) {
    extern __shared__ char sm[];
    __shared__ float bs1[H], bs2[H];
    int tid = threadIdx.x;
    int nb = blockIdx.x * TILE_M;
    if (tid < H) { bs1[tid] = b1[tid]; bs2[tid] = b2[tid]; }

    stage_B(sm, wpk1, tid);
    for (int idx = tid; idx < TILE_M * 32; idx += 512) {
        int node = idx >> 5, c = idx & 31;
        int gn = nb + node;
        float4 val = (gn < n) ? ((const float4*)A)[(size_t)gn * 32 + c]
                              : make_float4(0.f, 0.f, 0.f, 0.f);
        store_A4(sm, node, c, val);
    }
    __syncthreads();

    int wid = tid >> 5;
    int node = tid >> 2, cb = (tid & 3) * 32;
    int gn = nb + node;
    wmma::fragment<wmma::accumulator, 16, 16, 16, float> acc[2][2];

    // set 1: h = ssp(agg@W1 + b1)
    mma_set(sm, wid, acc);
    __syncthreads();
    store_set(sm, wid, acc);
    __syncthreads();

    float t1[32];
    {
        const float* ip = (const float*)(sm + SM_AHI) + node * OL + cb;
#pragma unroll
        for (int i = 0; i < 32; i++) t1[i] = sspf(ip[i] + bs1[cb + i]);
    }
    __syncthreads();
#pragma unroll
    for (int i = 0; i < 8; i++)
        store_A4(sm, node, (cb >> 2) + i,
                 make_float4(t1[4 * i], t1[4 * i + 1], t1[4 * i + 2], t1[4 * i + 3]));
    stage_B(sm, wpk2, tid);
    __syncthreads();

    // set 2: o = h@W2 + b2 + v   (write v)
    mma_set(sm, wid, acc);
    __syncthreads();
    store_set(sm, wid, acc);
    __syncthreads();

    float o[32];
    {
        const float* ip = (const float*)(sm + SM_AHI) + node * OL + cb;
        if (gn < n) {
            const float* rp = v + (size_t)gn * H + cb;
#pragma unroll
            for (int i = 0; i < 32; i++) o[i] = ip[i] + bs2[cb + i] + rp[i];
            float4* op = (float4*)(v + (size_t)gn * H + cb);
#pragma unroll
            for (int i = 0; i < 8; i++)
                op[i] = make_float4(o[4 * i], o[4 * i + 1], o[4 * i + 2], o[4 * i + 3]);
        } else {
#pragma unroll
            for (int i = 0; i < 32; i++) o[i] = 0.f;
        }
    }
    __syncthreads();
#pragma unroll
    for (int i = 0; i < 8; i++)
        store_A4(sm, node, (cb >> 2) + i,
                 make_float4(o[4 * i], o[4 * i + 1], o[4 * i + 2], o[4 * i + 3]));
    stage_B(sm, wpkL, tid);
    __syncthreads();

    // set 3: vlin = v_new @ linW
    mma_set(sm, wid, acc);
    __syncthreads();
    store_set(sm, wid, acc);
    __syncthreads();

    if (gn < n) {
        const float* ip = (const float*)(sm + SM_AHI) + node * OL + cb;
        float4* op = (float4*)(vlin + (size_t)gn * H + cb);
#pragma unroll
        for (int i = 0; i < 8; i++)
            op[i] = make_float4(ip[4 * i], ip[4 * i + 1], ip[4 * i + 2], ip[4 * i + 3]);
    }
}

// ---------------- mlp_readout_fused (layer 1 + readout) ----------------
__global__ void __launch_bounds__(512, 1) mlp_readout_fused(const float* __restrict__ A,
                                                            const uint32_t* __restrict__ wpk1,
                                                            const float* __restrict__ b1,
                                                            const uint32_t* __restrict__ wpk2,
                                                            const float* __restrict__ b2,
                                                            const float* __restrict__ v,
                                                            const uint32_t* __restrict__ wpkU,
                                                            const float* __restrict__ bu,
                                                            const float* __restrict__ U2,
                                                            const float* __restrict__ b2u,
                                                            float* __restrict__ out, int n) {
    extern __shared__ char sm[];
    __shared__ float bs1[H], bs2[H], bsu[H], ws2[H * 3];
    int tid = threadIdx.x;
    int nb = blockIdx.x * TILE_M;
    if (tid < H) { bs1[tid] = b1[tid]; bs2[tid] = b2[tid]; bsu[tid] = bu[tid]; }
    for (int idx = tid; idx < H * 3; idx += 512) ws2[idx] = U2[idx];

    stage_B(sm, wpk1, tid);
    for (int idx = tid; idx < TILE_M * 32; idx += 512) {
        int node = idx >> 5, c = idx & 31;
        int gn = nb + node;
        float4 val = (gn < n) ? ((const float4*)A)[(size_t)gn * 32 + c]
                              : make_float4(0.f, 0.f, 0.f, 0.f);
        store_A4(sm, node, c, val);
    }
    __syncthreads();

    int wid = tid >> 5;
    int node = tid >> 2, cb = (tid & 3) * 32;
    int gn = nb + node;
    wmma::fragment<wmma::accumulator, 16, 16, 16, float> acc[2][2];

    // set 1
    mma_set(sm, wid, acc);
    __syncthreads();
    store_set(sm, wid, acc);
    __syncthreads();

    float t1[32];
    {
        const float* ip = (const float*)(sm + SM_AHI) + node * OL + cb;
#pragma unroll
        for (int i = 0; i < 32; i++) t1[i] = sspf(ip[i] + bs1[cb + i]);
    }
    __syncthreads();
#pragma unroll
    for (int i = 0; i < 8; i++)
        store_A4(sm, node, (cb >> 2) + i,
                 make_float4(t1[4 * i], t1[4 * i + 1], t1[4 * i + 2], t1[4 * i + 3]));
    stage_B(sm, wpk2, tid);
    __syncthreads();

    // set 2: vn = h@W2 + b2 + v   (no global write)
    mma_set(sm, wid, acc);
    __syncthreads();
    store_set(sm, wid, acc);
    __syncthreads();

    float o[32];
    {
        const float* ip = (const float*)(sm + SM_AHI) + node * OL + cb;
        if (gn < n) {
            const float* rp = v + (size_t)gn * H + cb;
#pragma unroll
            for (int i = 0; i < 32; i++) o[i] = ip[i] + bs2[cb + i] + rp[i];
        } else {
#pragma unroll
            for (int i = 0; i < 32; i++) o[i] = 0.f;
        }
    }
    __syncthreads();
#pragma unroll
    for (int i = 0; i < 8; i++)
        store_A4(sm, node, (cb >> 2) + i,
                 make_float4(o[4 * i], o[4 * i + 1], o[4 * i + 2], o[4 * i + 3]));
    stage_B(sm, wpkU, tid);
    __syncthreads();

    // set 3: hu = ssp(vn@U1 + bu); project to 3, reduce over 4 threads/node
    mma_set(sm, wid, acc);
    __syncthreads();
    store_set(sm, wid, acc);
    __syncthreads();

    float p0 = 0.f, p1 = 0.f, p2 = 0.f;
    {
        const float* ip = (const float*)(sm + SM_AHI) + node * OL + cb;
#pragma unroll
        for (int i = 0; i < 32; i++) {
            float x = sspf(ip[i] + bsu[cb + i]);
            int col = cb + i;
            p0 += x * ws2[col * 3 + 0];
            p1 += x * ws2[col * 3 + 1];
            p2 += x * ws2[col * 3 + 2];
        }
    }
#pragma unroll
    for (int off = 2; off; off >>= 1) {
        p0 += __shfl_down_sync(0xffffffffu, p0, off, 4);
        p1 += __shfl_down_sync(0xffffffffu, p1, off, 4);
        p2 += __shfl_down_sync(0xffffffffu, p2, off, 4);
    }
    if ((tid & 3) == 0 && gn < n) {
        out[gn * 3 + 0] = p0 + b2u[0];
        out[gn * 3 + 1] = p1 + b2u[1];
        out[gn * 3 + 2] = p2 + b2u[2];
    }
}

// ---------------- filter table ----------------
__global__ void table_kernel(const float* __restrict__ m0w0, const float* __restrict__ m0b0,
                             const float* __restrict__ m2w0, const float* __restrict__ m2b0,
                             const float* __restrict__ m0w1, const float* __restrict__ m0b1,
                             const float* __restrict__ m2w1, const float* __restrict__ m2b1,
                             float* __restrict__ wtab) {
    int l = blockIdx.x / NBINS;
    int t = blockIdx.x % NBINS;
    const float* m0w = l ? m0w1 : m0w0;
    const float* m0b = l ? m0b1 : m0b0;
    const float* m2w = l ? m2w1 : m2w0;
    const float* m2b = l ? m2b1 : m2b0;
    __shared__ float hs[H];
    int h = threadIdx.x;
    const float step = CUTOFF / (float)(G_RBF - 1);
    const float coeff = -0.5f / (step * step);
    float acc = m0b[h];
#pragma unroll 10
    for (int g = 0; g < G_RBF; g++) {
        float dd = (float)t - step * (float)g;
        acc += expf(coeff * dd * dd) * m0w[g * H + h];
    }
    hs[h] = sspf(acc);
    __syncthreads();
    float o = m2b[h];
#pragma unroll 16
    for (int k = 0; k < H; k++) o += hs[k] * m2w[k * H + h];
    wtab[(l * NBINS + t) * H + h] = o;
}

// ---------------- CSR build ----------------
__global__ void zero_cnt_kernel(int* __restrict__ cnt) {
    int i = blockIdx.x * blockDim.x + threadIdx.x;
    if (i < N_NODES) cnt[i] = 0;
}
__global__ void hist_kernel(const int* __restrict__ ei, int* __restrict__ cnt) {
    int e = blockIdx.x * blockDim.x + threadIdx.x;
    if (e < N_EDGES) atomicAdd(&cnt[ei[N_EDGES + e]], 1);
}
__global__ void scan1_kernel(const int* __restrict__ cnt, int* __restrict__ off,
                             int* __restrict__ bsum) {
    __shared__ int s[256];
    int t = threadIdx.x;
    int i = blockIdx.x * 256 + t;
    int v = (i < N_NODES) ? cnt[i] : 0;
    s[t] = v;
    __syncthreads();
#pragma unroll
    for (int o = 1; o < 256; o <<= 1) {
        int x = (t >= o) ? s[t - o] : 0;
        __syncthreads();
        s[t] += x;
        __syncthreads();
    }
    if (i < N_NODES) off[i] = s[t] - v;
    if (t == 255) bsum[blockIdx.x] = s[255];
}
__global__ void scan2_kernel(int* __restrict__ bsum) {
    __shared__ int s[256];
    int t = threadIdx.x;
    int v = (t < SCAN_BLOCKS) ? bsum[t] : 0;
    s[t] = v;
    __syncthreads();
#pragma unroll
    for (int o = 1; o < 256; o <<= 1) {
        int x = (t >= o) ? s[t - o] : 0;
        __syncthreads();
        s[t] += x;
        __syncthreads();
    }
    if (t < SCAN_BLOCKS) bsum[t] = s[t] - v;
}
__global__ void scan3_kernel(int* __restrict__ off, const int* __restrict__ bsum,
                             int* __restrict__ pos) {
    int i = blockIdx.x * blockDim.x + threadIdx.x;
    if (i < N_NODES) {
        int o = off[i] + bsum[i >> 8];
        off[i] = o;
        pos[i] = o;
    }
    if (i == 0) off[N_NODES] = N_EDGES;
}
__global__ void scatter_kernel(const int* __restrict__ ei, const float* __restrict__ dist,
                               int* __restrict__ pos, int* __restrict__ jt,
                               float* __restrict__ cs) {
    int e = blockIdx.x * blockDim.x + threadIdx.x;
    if (e >= N_EDGES) return;
    int j = ei[e];
    int i = ei[N_EDGES + e];
    float d = dist[e];
    int tb = (int)d;
    if (tb > NBINS - 1) tb = NBINS - 1;
    float C = 0.5f * cosf(d * (PI_F / CUTOFF)) + 0.5f;
    int p = atomicAdd(&pos[i], 1);
    jt[p] = j | (tb << 27);
    cs[p] = C;
}

// ---------------- aggregate (fp32 vlin) ----------------
__global__ void __launch_bounds__(256) agg_kernel(const float* __restrict__ vlin,
                                                  const int* __restrict__ off,
                                                  const int* __restrict__ jt,
                                                  const float* __restrict__ cs,
                                                  const float* __restrict__ wtab,
                                                  float* __restrict__ agg) {
    __shared__ float4 ws[NBINS * 32];
    int tid = threadIdx.x;
    if (tid < NBINS * 32) ws[tid] = ((const float4*)wtab)[tid];
    __syncthreads();

    int node = blockIdx.x * 8 + (tid >> 5);
    if (node >= N_NODES) return;
    int lane = tid & 31;
    int s = off[node], e = off[node + 1];
    float4 acc = make_float4(0.f, 0.f, 0.f, 0.f);
    const float4* vlin4 = (const float4*)vlin;

    for (int base = s; base < e; base += 32) {
        int m = min(32, e - base);
        int mj = (lane < m) ? jt[base + lane] : 0;
        float mc = (lane < m) ? cs[base + lane] : 0.f;
        int t = 0;
        for (; t + 4 <= m; t += 4) {
            int jv0 = __shfl_sync(0xffffffffu, mj, t);
            int jv1 = __shfl_sync(0xffffffffu, mj, t + 1);
            int jv2 = __shfl_sync(0xffffffffu, mj, t + 2);
            int jv3 = __shfl_sync(0xffffffffu, mj, t + 3);
            float c0 = __shfl_sync(0xffffffffu, mc, t);
            float c1 = __shfl_sync(0xffffffffu, mc, t + 1);
            float c2 = __shfl_sync(0xffffffffu, mc, t + 2);
            float c3 = __shfl_sync(0xffffffffu, mc, t + 3);
            float4 x0 = __ldg(vlin4 + (size_t)(jv0 & 0x07FFFFFF) * 32 + lane);
            float4 x1 = __ldg(vlin4 + (size_t)(jv1 & 0x07FFFFFF) * 32 + lane);
            float4 x2 = __ldg(vlin4 + (size_t)(jv2 & 0x07FFFFFF) * 32 + lane);
            float4 x3 = __ldg(vlin4 + (size_t)(jv3 & 0x07FFFFFF) * 32 + lane);
            float4 w0 = ws[(jv0 >> 27) * 32 + lane];
            float4 w1 = ws[(jv1 >> 27) * 32 + lane];
            float4 w2 = ws[(jv2 >> 27) * 32 + lane];
            float4 w3 = ws[(jv3 >> 27) * 32 + lane];
            acc.x += x0.x * w0.x * c0; acc.y += x0.y * w0.y * c0;
            acc.z += x0.z * w0.z * c0; acc.w += x0.w * w0.w * c0;
            acc.x += x1.x * w1.x * c1; acc.y += x1.y * w1.y * c1;
            acc.z += x1.z * w1.z * c1; acc.w += x1.w * w1.w * c1;
            acc.x += x2.x * w2.x * c2; acc.y += x2.y * w2.y * c2;
            acc.z += x2.z * w2.z * c2; acc.w += x2.w * w2.w * c2;
            acc.x += x3.x * w3.x * c3; acc.y += x3.y * w3.y * c3;
            acc.z += x3.z * w3.z * c3; acc.w += x3.w * w3.w * c3;
        }
        for (; t < m; t++) {
            int jv = __shfl_sync(0xffffffffu, mj, t);
            float c = __shfl_sync(0xffffffffu, mc, t);
            float4 x = __ldg(vlin4 + (size_t)(jv & 0x07FFFFFF) * 32 + lane);
            float4 w = ws[(jv >> 27) * 32 + lane];
            acc.x += x.x * w.x * c;
            acc.y += x.y * w.y * c;
            acc.z += x.z * w.z * c;
            acc.w += x.w * w.w * c;
        }
    }
    ((float4*)agg)[(size_t)node * 32 + lane] = acc;
}

// ---------------- launch ----------------
extern "C" void kernel_launch(void* const* d_in, const int* in_sizes, int n_in,
                              void* d_out, int out_size) {
    const float* z        = (const float*)d_in[0];
    const float* dist     = (const float*)d_in[1];
    const int*   ei       = (const int*)d_in[2];
    const float* init_w   = (const float*)d_in[3];
    const float* init_b   = (const float*)d_in[4];
    const float* e_lin_w[2] = {(const float*)d_in[5],  (const float*)d_in[14]};
    const float* e_m0_w[2]  = {(const float*)d_in[6],  (const float*)d_in[15]};
    const float* e_m0_b[2]  = {(const float*)d_in[7],  (const float*)d_in[16]};
    const float* e_m2_w[2]  = {(const float*)d_in[8],  (const float*)d_in[17]};
    const float* e_m2_b[2]  = {(const float*)d_in[9],  (const float*)d_in[18]};
    const float* v_l1_w[2]  = {(const float*)d_in[10], (const float*)d_in[19]};
    const float* v_l1_b[2]  = {(const float*)d_in[11], (const float*)d_in[20]};
    const float* v_l2_w[2]  = {(const float*)d_in[12], (const float*)d_in[21]};
    const float* v_l2_b[2]  = {(const float*)d_in[13], (const float*)d_in[22]};
    const float* u_l1_w   = (const float*)d_in[23];
    const float* u_l1_b   = (const float*)d_in[24];
    const float* u_l2_w   = (const float*)d_in[25];
    const float* u_l2_b   = (const float*)d_in[26];
    float* out = (float*)d_out;

    float *v, *vlin, *agg, *wtab, *cs;
    uint32_t* wpk;
    int *cnt, *off, *pos, *bsum, *jt;
    cudaGetSymbolAddress((void**)&v,    g_v);
    cudaGetSymbolAddress((void**)&vlin, g_vlin);
    cudaGetSymbolAddress((void**)&agg,  g_agg);
    cudaGetSymbolAddress((void**)&wtab, g_wtab);
    cudaGetSymbolAddress((void**)&wpk,  g_wpk);
    cudaGetSymbolAddress((void**)&cnt,  g_cnt);
    cudaGetSymbolAddress((void**)&off,  g_off);
    cudaGetSymbolAddress((void**)&pos,  g_pos);
    cudaGetSymbolAddress((void**)&bsum, g_bsum);
    cudaGetSymbolAddress((void**)&jt,   g_jt);
    cudaGetSymbolAddress((void**)&cs,   g_cs);

    cudaFuncSetAttribute((const void*)gemm0_fused,
                         cudaFuncAttributeMaxDynamicSharedMemorySize, TCG_SMEM);
    cudaFuncSetAttribute((const void*)mlp_fused,
                         cudaFuncAttributeMaxDynamicSharedMemorySize, TCG_SMEM);
    cudaFuncSetAttribute((const void*)mlp_readout_fused,
                         cudaFuncAttributeMaxDynamicSharedMemorySize, TCG_SMEM);

    const int egrid = (N_EDGES + 255) / 256;
    const int ngrid = (N_NODES + 255) / 256;
    const uint32_t* wm[7];  // 0:e_lin0 1:l1_0 2:l2_0 3:e_lin1 4:l1_1 5:l2_1 6:u1
    for (int i = 0; i < 7; i++) wm[i] = wpk + (size_t)i * WIMG_U32;

    table_kernel<<<2 * NBINS, H>>>(e_m0_w[0], e_m0_b[0], e_m2_w[0], e_m2_b[0],      // 0
                                   e_m0_w[1], e_m0_b[1], e_m2_w[1], e_m2_b[1], wtab);
    {
        dim3 wg(32, 7);
        wsplit_kernel<<<wg, 256>>>(e_lin_w[0], v_l1_w[0], v_l2_w[0],                 // 1
                                   e_lin_w[1], v_l1_w[1], v_l2_w[1], u_l1_w, wpk);
    }
    zero_cnt_kernel<<<ngrid, 256>>>(cnt);                                            // 2
    gemm0_fused<<<N_TILES, 512, TCG_SMEM>>>(z, init_w, init_b, wm[0],                // 3 <- profiled
                                            v, vlin, N_NODES);
    hist_kernel<<<egrid, 256>>>(ei, cnt);                                            // 4
    scan1_kernel<<<SCAN_BLOCKS, 256>>>(cnt, off, bsum);                              // 5
    scan2_kernel<<<1, 256>>>(bsum);                                                  // 6
    scan3_kernel<<<SCAN_BLOCKS, 256>>>(off, bsum, pos);                              // 7
    scatter_kernel<<<egrid, 256>>>(ei, dist, pos, jt, cs);                           // 8

    // layer 0: fused l1 -> ssp -> l2 (+v) -> vlin = v @ e_lin1
    agg_kernel<<<(N_NODES + 7) / 8, 256>>>(vlin, off, jt, cs, wtab, agg);            // 9
    mlp_fused<<<N_TILES, 512, TCG_SMEM>>>(agg, wm[1], v_l1_b[0],                     // 10
                                          wm[2], v_l2_b[0], v, wm[3], vlin, N_NODES);
    // layer 1 + readout fused
    agg_kernel<<<(N_NODES + 7) / 8, 256>>>(vlin, off, jt, cs, wtab + NBINS * H, agg);// 11
    mlp_readout_fused<<<N_TILES, 512, TCG_SMEM>>>(agg, wm[4], v_l1_b[1],             // 12
                                                  wm[5], v_l2_b[1], v,
                                                  wm[6], u_l1_b, u_l2_w, u_l2_b,
                                                  out, N_NODES);
}

// round 16
// speedup vs baseline: 1.0670x; 1.0670x over previous
#include <cuda_runtime.h>
#include <cuda_bf16.h>
#include <mma.h>
#include <math.h>
#include <stdint.h>

using namespace nvcuda;

#define N_NODES 50000
#define N_EDGES 800000
#define H 128
#define G_RBF 50
#define NBINS 7
#define CUTOFF 6.0f
#define SSP_SHIFT 0.6931471805599453f
#define PI_F 3.14159265358979323846f

#define SCAN_BLOCKS ((N_NODES + 255) / 256)   // 196
#define TILE_M 64
#define N_TILES ((N_NODES + TILE_M - 1) / TILE_M)   // 782
#define WL 136            // bf16 leading dim (128 + 8 pad)
#define OL 132            // f32 output leading dim (128 + 4 pad)
#define WIMG_U32 17408    // per-matrix packed image: hi(8704 u32) + lo(8704 u32)

// smem layout (bytes)
#define SM_AHI 0
#define SM_ALO (TILE_M * WL * 2)                 // 17408
#define SM_BHI (2 * TILE_M * WL * 2)             // 34816
#define SM_BLO (SM_BHI + H * WL * 2)
#define TCG_SMEM (SM_BHI + 2 * H * WL * 2)       // 104448

// ---------------- scratch ----------------
__device__ float  g_v[N_NODES * H];
__device__ float  g_vlin[N_NODES * H];    // layer-0 edge features (read-only during mlp_fused)
__device__ float  g_vlin2[N_NODES * H];   // layer-1 edge features (written by mlp_fused)
__device__ float  g_wtab[2 * NBINS * H];
__device__ uint32_t g_wpk[7 * WIMG_U32];
__device__ int   g_cnt[N_NODES];
__device__ int   g_off[N_NODES + 1];
__device__ int   g_pos[N_NODES];
__device__ int   g_bsum[SCAN_BLOCKS];
__device__ int   g_jt[N_EDGES];
__device__ float g_cs[N_EDGES];

__device__ __forceinline__ float sspf(float x) {
    return fmaxf(x, 0.0f) + log1pf(expf(-fabsf(x))) - SSP_SHIFT;
}

__device__ __forceinline__ uint32_t pack_bf16x2(float x0, float x1) {
    __nv_bfloat16 h0 = __float2bfloat16_rn(x0);
    __nv_bfloat16 h1 = __float2bfloat16_rn(x1);
    return (uint32_t)__bfloat16_as_ushort(h0) |
           ((uint32_t)__bfloat16_as_ushort(h1) << 16);
}

// ---------------- W pre-split ----------------
__global__ void wsplit_kernel(const float* __restrict__ w0, const float* __restrict__ w1,
                              const float* __restrict__ w2, const float* __restrict__ w3,
                              const float* __restrict__ w4, const float* __restrict__ w5,
                              const float* __restrict__ w6, uint32_t* __restrict__ wpk) {
    const float* ws[7] = {w0, w1, w2, w3, w4, w5, w6};
    int m = blockIdx.y;
    const float* W = ws[m];
    int t = blockIdx.x * 256 + threadIdx.x;
    if (t >= 8192) return;
    int n = t & 127;
    int kp = t >> 7;
    float x0 = W[(2 * kp) * H + n];
    float x1 = W[(2 * kp + 1) * H + n];
    float h0 = __bfloat162float(__float2bfloat16_rn(x0));
    float h1 = __bfloat162float(__float2bfloat16_rn(x1));
    uint32_t* base = wpk + (size_t)m * WIMG_U32;
    base[(n * WL + 2 * kp) >> 1]          = pack_bf16x2(x0, x1);
    base[8704 + ((n * WL + 2 * kp) >> 1)] = pack_bf16x2(x0 - h0, x1 - h1);
}

// ================= shared building blocks =================
__device__ __forceinline__ void stage_B(char* sm, const uint32_t* wpk, int tid) {
    const float4* src = (const float4*)wpk;
    float4* dst = (float4*)(sm + SM_BHI);
    for (int i = tid; i < (2 * H * WL * 2) / 16; i += 512) dst[i] = src[i];
}

__device__ __forceinline__ void store_A4(char* sm, int node, int c, float4 a) {
    float hx = __bfloat162float(__float2bfloat16_rn(a.x));
    float hy = __bfloat162float(__float2bfloat16_rn(a.y));
    float hz = __bfloat162float(__float2bfloat16_rn(a.z));
    float hw = __bfloat162float(__float2bfloat16_rn(a.w));
    uint32_t boff = 2 * (node * WL + 4 * c);
    *(uint2*)(sm + SM_AHI + boff) = make_uint2(pack_bf16x2(a.x, a.y), pack_bf16x2(a.z, a.w));
    *(uint2*)(sm + SM_ALO + boff) = make_uint2(pack_bf16x2(a.x - hx, a.y - hy),
                                               pack_bf16x2(a.z - hz, a.w - hw));
}

__device__ __forceinline__ void mma_set(const char* sm, int wid,
        wmma::fragment<wmma::accumulator, 16, 16, 16, float>* acc) {
    int wrow = wid & 3, wcol = wid >> 2;
    const __nv_bfloat16* Ahi = (const __nv_bfloat16*)(sm + SM_AHI) + wrow * 16 * WL;
    const __nv_bfloat16* Alo = (const __nv_bfloat16*)(sm + SM_ALO) + wrow * 16 * WL;
    const __nv_bfloat16* Bhi = (const __nv_bfloat16*)(sm + SM_BHI);
    const __nv_bfloat16* Blo = (const __nv_bfloat16*)(sm + SM_BLO);
#pragma unroll
    for (int t = 0; t < 2; t++) wmma::fill_fragment(acc[t], 0.0f);
#pragma unroll
    for (int ks = 0; ks < 8; ks++) {
        wmma::fragment<wmma::matrix_a, 16, 16, 16, __nv_bfloat16, wmma::row_major> ah, al;
        wmma::load_matrix_sync(ah, Ahi + ks * 16, WL);
        wmma::load_matrix_sync(al, Alo + ks * 16, WL);
#pragma unroll
        for (int t = 0; t < 2; t++) {
            int ncol = wcol * 32 + t * 16;
            wmma::fragment<wmma::matrix_b, 16, 16, 16, __nv_bfloat16, wmma::col_major> bh, bl;
            wmma::load_matrix_sync(bh, Bhi + ncol * WL + ks * 16, WL);
            wmma::load_matrix_sync(bl, Blo + ncol * WL + ks * 16, WL);
            wmma::mma_sync(acc[t], ah, bh, acc[t]);
            wmma::mma_sync(acc[t], ah, bl, acc[t]);
            wmma::mma_sync(acc[t], al, bh, acc[t]);
        }
    }
}

__device__ __forceinline__ void store_set(char* sm, int wid,
        wmma::fragment<wmma::accumulator, 16, 16, 16, float>* acc) {
    int wrow = wid & 3, wcol = wid >> 2;
    float* osm = (float*)(sm + SM_AHI);
#pragma unroll
    for (int t = 0; t < 2; t++)
        wmma::store_matrix_sync(osm + wrow * 16 * OL + wcol * 32 + t * 16,
                                acc[t], OL, wmma::mem_row_major);
}

// in-kernel gather of one node's aggregated edge features (warp-collective)
__device__ __forceinline__ float4 gather_node(const float4* __restrict__ vlin4,
                                              const int* __restrict__ off,
                                              const int* __restrict__ jt,
                                              const float* __restrict__ cs,
                                              const float4* wsg,
                                              int gnode, int lane) {
    float4 acc = make_float4(0.f, 0.f, 0.f, 0.f);
    int s = off[gnode], e = off[gnode + 1];
    for (int base = s; base < e; base += 32) {
        int m = min(32, e - base);
        int mj = (lane < m) ? jt[base + lane] : 0;
        float mc = (lane < m) ? cs[base + lane] : 0.f;
        int t = 0;
        for (; t + 4 <= m; t += 4) {
            int jv0 = __shfl_sync(0xffffffffu, mj, t);
            int jv1 = __shfl_sync(0xffffffffu, mj, t + 1);
            int jv2 = __shfl_sync(0xffffffffu, mj, t + 2);
            int jv3 = __shfl_sync(0xffffffffu, mj, t + 3);
            float c0 = __shfl_sync(0xffffffffu, mc, t);
            float c1 = __shfl_sync(0xffffffffu, mc, t + 1);
            float c2 = __shfl_sync(0xffffffffu, mc, t + 2);
            float c3 = __shfl_sync(0xffffffffu, mc, t + 3);
            float4 x0 = __ldg(vlin4 + (size_t)(jv0 & 0x07FFFFFF) * 32 + lane);
            float4 x1 = __ldg(vlin4 + (size_t)(jv1 & 0x07FFFFFF) * 32 + lane);
            float4 x2 = __ldg(vlin4 + (size_t)(jv2 & 0x07FFFFFF) * 32 + lane);
            float4 x3 = __ldg(vlin4 + (size_t)(jv3 & 0x07FFFFFF) * 32 + lane);
            float4 w0 = wsg[(jv0 >> 27) * 32 + lane];
            float4 w1 = wsg[(jv1 >> 27) * 32 + lane];
            float4 w2 = wsg[(jv2 >> 27) * 32 + lane];
            float4 w3 = wsg[(jv3 >> 27) * 32 + lane];
            acc.x += x0.x * w0.x * c0; acc.y += x0.y * w0.y * c0;
            acc.z += x0.z * w0.z * c0; acc.w += x0.w * w0.w * c0;
            acc.x += x1.x * w1.x * c1; acc.y += x1.y * w1.y * c1;
            acc.z += x1.z * w1.z * c1; acc.w += x1.w * w1.w * c1;
            acc.x += x2.x * w2.x * c2; acc.y += x2.y * w2.y * c2;
            acc.z += x2.z * w2.z * c2; acc.w += x2.w * w2.w * c2;
            acc.x += x3.x * w3.x * c3; acc.y += x3.y * w3.y * c3;
            acc.z += x3.z * w3.z * c3; acc.w += x3.w * w3.w * c3;
        }
        for (; t < m; t++) {
            int jv = __shfl_sync(0xffffffffu, mj, t);
            float c = __shfl_sync(0xffffffffu, mc, t);
            float4 x = __ldg(vlin4 + (size_t)(jv & 0x07FFFFFF) * 32 + lane);
            float4 w = wsg[(jv >> 27) * 32 + lane];
            acc.x += x.x * w.x * c;
            acc.y += x.y * w.y * c;
            acc.z += x.z * w.z * c;
            acc.w += x.w * w.w * c;
        }
    }
    return acc;
}

// ---------------- gemm0_fused: v = z@iw+ib (written), vlin = v @ e_lin0 ----------------
__global__ void __launch_bounds__(512, 2) gemm0_fused(const float* __restrict__ z,
                                                      const float* __restrict__ iw,
                                                      const float* __restrict__ ib,
                                                      const uint32_t* __restrict__ wpk,
                                                      float* __restrict__ vout,
                                                      float* __restrict__ vlin, int n) {
    extern __shared__ char sm[];
    int tid = threadIdx.x;
    int nb = blockIdx.x * TILE_M;

    stage_B(sm, wpk, tid);
    for (int idx = tid; idx < TILE_M * 32; idx += 512) {
        int node = idx >> 5, c = idx & 31;
        int gn = nb + node;
        float4 val = make_float4(0.f, 0.f, 0.f, 0.f);
        if (gn < n) {
            float z0 = __ldg(z + gn * 3), z1 = __ldg(z + gn * 3 + 1), z2 = __ldg(z + gn * 3 + 2);
            float4 b  = __ldg((const float4*)ib + c);
            float4 w0 = __ldg((const float4*)iw + c);
            float4 w1 = __ldg((const float4*)iw + 32 + c);
            float4 w2 = __ldg((const float4*)iw + 64 + c);
            val.x = b.x + z0 * w0.x + z1 * w1.x + z2 * w2.x;
            val.y = b.y + z0 * w0.y + z1 * w1.y + z2 * w2.y;
            val.z = b.z + z0 * w0.z + z1 * w1.z + z2 * w2.z;
            val.w = b.w + z0 * w0.w + z1 * w1.w + z2 * w2.w;
            ((float4*)vout)[(size_t)gn * 32 + c] = val;
        }
        store_A4(sm, node, c, val);
    }
    __syncthreads();

    int wid = tid >> 5;
    wmma::fragment<wmma::accumulator, 16, 16, 16, float> acc[2];
    mma_set(sm, wid, acc);
    __syncthreads();
    store_set(sm, wid, acc);
    __syncthreads();

    int node = tid >> 3, cb = (tid & 7) * 16;
    int gn = nb + node;
    if (gn < n) {
        const float* ip = (const float*)(sm + SM_AHI) + node * OL + cb;
        float4* op = (float4*)(vlin + (size_t)gn * H + cb);
#pragma unroll
        for (int i = 0; i < 4; i++)
            op[i] = make_float4(ip[4 * i], ip[4 * i + 1], ip[4 * i + 2], ip[4 * i + 3]);
    }
}

// ---------------- mlp_fused (layer 0, gather fused): ----------------
// agg = gather(vlin_in); v += ssp(agg@W1+b1)@W2+b2 ; vlin_out = v@linW
// vlin_in is read-only here; vlin_out is a DIFFERENT buffer (no cross-block hazard)
__global__ void __launch_bounds__(512, 2) mlp_fused(const int* __restrict__ off,
                                                    const int* __restrict__ jt,
                                                    const float* __restrict__ cs,
                                                    const float* __restrict__ wtab,
                                                    const float* __restrict__ vlin_in,
                                                    const uint32_t* __restrict__ wpk1,
                                                    const float* __restrict__ b1,
                                                    const uint32_t* __restrict__ wpk2,
                                                    const float* __restrict__ b2,
                                                    float* __restrict__ v,
                                                    const uint32_t* __restrict__ wpkL,
                                                    float* __restrict__ vlin_out, int n) {
    extern __shared__ char sm[];
    __shared__ float bs1[H], bs2[H];
    __shared__ float4 wsg[NBINS * 32];
    int tid = threadIdx.x;
    int nb = blockIdx.x * TILE_M;
    if (tid < H) { bs1[tid] = b1[tid]; bs2[tid] = b2[tid]; }
    if (tid < NBINS * 32) wsg[tid] = ((const float4*)wtab)[tid];
    __syncthreads();   // wsg visible to gather

    stage_B(sm, wpk1, tid);

    int wid = tid >> 5, lane = tid & 31;
    const float4* vlin4 = (const float4*)vlin_in;
    // gather agg tile directly into A region (warp per node, 4 nodes/warp)
    for (int nn = wid; nn < TILE_M; nn += 16) {
        int gnode = nb + nn;
        float4 a = make_float4(0.f, 0.f, 0.f, 0.f);
        if (gnode < n) a = gather_node(vlin4, off, jt, cs, wsg, gnode, lane);
        store_A4(sm, nn, lane, a);
    }
    __syncthreads();

    int node = tid >> 3, cb = (tid & 7) * 16;
    int gn = nb + node;
    wmma::fragment<wmma::accumulator, 16, 16, 16, float> acc[2];

    // set 1: h = ssp(agg@W1 + b1)
    mma_set(sm, wid, acc);
    __syncthreads();
    store_set(sm, wid, acc);
    __syncthreads();

    float t1[16];
    {
        const float* ip = (const float*)(sm + SM_AHI) + node * OL + cb;
#pragma unroll
        for (int i = 0; i < 16; i++) t1[i] = sspf(ip[i] + bs1[cb + i]);
    }
    __syncthreads();
#pragma unroll
    for (int i = 0; i < 4; i++)
        store_A4(sm, node, (cb >> 2) + i,
                 make_float4(t1[4 * i], t1[4 * i + 1], t1[4 * i + 2], t1[4 * i + 3]));
    stage_B(sm, wpk2, tid);
    __syncthreads();

    // set 2: o = h@W2 + b2 + v   (write v)
    mma_set(sm, wid, acc);
    __syncthreads();
    store_set(sm, wid, acc);
    __syncthreads();

    float o[16];
    {
        const float* ip = (const float*)(sm + SM_AHI) + node * OL + cb;
        if (gn < n) {
            const float* rp = v + (size_t)gn * H + cb;
#pragma unroll
            for (int i = 0; i < 16; i++) o[i] = ip[i] + bs2[cb + i] + rp[i];
            float4* op = (float4*)(v + (size_t)gn * H + cb);
#pragma unroll
            for (int i = 0; i < 4; i++)
                op[i] = make_float4(o[4 * i], o[4 * i + 1], o[4 * i + 2], o[4 * i + 3]);
        } else {
#pragma unroll
            for (int i = 0; i < 16; i++) o[i] = 0.f;
        }
    }
    __syncthreads();
#pragma unroll
    for (int i = 0; i < 4; i++)
        store_A4(sm, node, (cb >> 2) + i,
                 make_float4(o[4 * i], o[4 * i + 1], o[4 * i + 2], o[4 * i + 3]));
    stage_B(sm, wpkL, tid);
    __syncthreads();

    // set 3: vlin_out = v_new @ linW
    mma_set(sm, wid, acc);
    __syncthreads();
    store_set(sm, wid, acc);
    __syncthreads();

    if (gn < n) {
        const float* ip = (const float*)(sm + SM_AHI) + node * OL + cb;
        float4* op = (float4*)(vlin_out + (size_t)gn * H + cb);
#pragma unroll
        for (int i = 0; i < 4; i++)
            op[i] = make_float4(ip[4 * i], ip[4 * i + 1], ip[4 * i + 2], ip[4 * i + 3]);
    }
}

// ---------------- mlp_readout_fused (layer 1 + readout, gather fused) ----------------
// gathers from vlin_in (read-only); writes only `out`
__global__ void __launch_bounds__(512, 2) mlp_readout_fused(const int* __restrict__ off,
                                                            const int* __restrict__ jt,
                                                            const float* __restrict__ cs,
                                                            const float* __restrict__ wtab,
                                                            const float* __restrict__ vlin_in,
                                                            const uint32_t* __restrict__ wpk1,
                                                            const float* __restrict__ b1,
                                                            const uint32_t* __restrict__ wpk2,
                                                            const float* __restrict__ b2,
                                                            const float* __restrict__ v,
                                                            const uint32_t* __restrict__ wpkU,
                                                            const float* __restrict__ bu,
                                                            const float* __restrict__ U2,
                                                            const float* __restrict__ b2u,
                                                            float* __restrict__ out, int n) {
    extern __shared__ char sm[];
    __shared__ float bs1[H], bs2[H], bsu[H], ws2[H * 3];
    __shared__ float4 wsg[NBINS * 32];
    int tid = threadIdx.x;
    int nb = blockIdx.x * TILE_M;
    if (tid < H) { bs1[tid] = b1[tid]; bs2[tid] = b2[tid]; bsu[tid] = bu[tid]; }
    for (int idx = tid; idx < H * 3; idx += 512) ws2[idx] = U2[idx];
    if (tid < NBINS * 32) wsg[tid] = ((const float4*)wtab)[tid];
    __syncthreads();

    stage_B(sm, wpk1, tid);

    int wid = tid >> 5, lane = tid & 31;
    const float4* vlin4 = (const float4*)vlin_in;
    for (int nn = wid; nn < TILE_M; nn += 16) {
        int gnode = nb + nn;
        float4 a = make_float4(0.f, 0.f, 0.f, 0.f);
        if (gnode < n) a = gather_node(vlin4, off, jt, cs, wsg, gnode, lane);
        store_A4(sm, nn, lane, a);
    }
    __syncthreads();

    int node = tid >> 3, cb = (tid & 7) * 16;
    int gn = nb + node;
    wmma::fragment<wmma::accumulator, 16, 16, 16, float> acc[2];

    // set 1
    mma_set(sm, wid, acc);
    __syncthreads();
    store_set(sm, wid, acc);
    __syncthreads();

    float t1[16];
    {
        const float* ip = (const float*)(sm + SM_AHI) + node * OL + cb;
#pragma unroll
        for (int i = 0; i < 16; i++) t1[i] = sspf(ip[i] + bs1[cb + i]);
    }
    __syncthreads();
#pragma unroll
    for (int i = 0; i < 4; i++)
        store_A4(sm, node, (cb >> 2) + i,
                 make_float4(t1[4 * i], t1[4 * i + 1], t1[4 * i + 2], t1[4 * i + 3]));
    stage_B(sm, wpk2, tid);
    __syncthreads();

    // set 2: vn = h@W2 + b2 + v   (no global write)
    mma_set(sm, wid, acc);
    __syncthreads();
    store_set(sm, wid, acc);
    __syncthreads();

    float o[16];
    {
        const float* ip = (const float*)(sm + SM_AHI) + node * OL + cb;
        if (gn < n) {
            const float* rp = v + (size_t)gn * H + cb;
#pragma unroll
            for (int i = 0; i < 16; i++) o[i] = ip[i] + bs2[cb + i] + rp[i];
        } else {
#pragma unroll
            for (int i = 0; i < 16; i++) o[i] = 0.f;
        }
    }
    __syncthreads();
#pragma unroll
    for (int i = 0; i < 4; i++)
        store_A4(sm, node, (cb >> 2) + i,
                 make_float4(o[4 * i], o[4 * i + 1], o[4 * i + 2], o[4 * i + 3]));
    stage_B(sm, wpkU, tid);
    __syncthreads();

    // set 3: hu = ssp(vn@U1 + bu); project to 3 and reduce
    mma_set(sm, wid, acc);
    __syncthreads();
    store_set(sm, wid, acc);
    __syncthreads();

    float p0 = 0.f, p1 = 0.f, p2 = 0.f;
    {
        const float* ip = (const float*)(sm + SM_AHI) + node * OL + cb;
#pragma unroll
        for (int i = 0; i < 16; i++) {
            float x = sspf(ip[i] + bsu[cb + i]);
            int col = cb + i;
            p0 += x * ws2[col * 3 + 0];
            p1 += x * ws2[col * 3 + 1];
            p2 += x * ws2[col * 3 + 2];
        }
    }
#pragma unroll
    for (int offs = 4; offs; offs >>= 1) {
        p0 += __shfl_down_sync(0xffffffffu, p0, offs, 8);
        p1 += __shfl_down_sync(0xffffffffu, p1, offs, 8);
        p2 += __shfl_down_sync(0xffffffffu, p2, offs, 8);
    }
    if ((tid & 7) == 0 && gn < n) {
        out[gn * 3 + 0] = p0 + b2u[0];
        out[gn * 3 + 1] = p1 + b2u[1];
        out[gn * 3 + 2] = p2 + b2u[2];
    }
}

// ---------------- filter table ----------------
__global__ void table_kernel(const float* __restrict__ m0w0, const float* __restrict__ m0b0,
                             const float* __restrict__ m2w0, const float* __restrict__ m2b0,
                             const float* __restrict__ m0w1, const float* __restrict__ m0b1,
                             const float* __restrict__ m2w1, const float* __restrict__ m2b1,
                             float* __restrict__ wtab) {
    int l = blockIdx.x / NBINS;
    int t = blockIdx.x % NBINS;
    const float* m0w = l ? m0w1 : m0w0;
    const float* m0b = l ? m0b1 : m0b0;
    const float* m2w = l ? m2w1 : m2w0;
    const float* m2b = l ? m2b1 : m2b0;
    __shared__ float hs[H];
    int h = threadIdx.x;
    const float step = CUTOFF / (float)(G_RBF - 1);
    const float coeff = -0.5f / (step * step);
    float acc = m0b[h];
#pragma unroll 10
    for (int g = 0; g < G_RBF; g++) {
        float dd = (float)t - step * (float)g;
        acc += expf(coeff * dd * dd) * m0w[g * H + h];
    }
    hs[h] = sspf(acc);
    __syncthreads();
    float o = m2b[h];
#pragma unroll 16
    for (int k = 0; k < H; k++) o += hs[k] * m2w[k * H + h];
    wtab[(l * NBINS + t) * H + h] = o;
}

// ---------------- CSR build ----------------
__global__ void zero_cnt_kernel(int* __restrict__ cnt) {
    int i = blockIdx.x * blockDim.x + threadIdx.x;
    if (i < N_NODES) cnt[i] = 0;
}
__global__ void hist_kernel(const int* __restrict__ ei, int* __restrict__ cnt) {
    int e = blockIdx.x * blockDim.x + threadIdx.x;
    if (e < N_EDGES) atomicAdd(&cnt[ei[N_EDGES + e]], 1);
}
__global__ void scan1_kernel(const int* __restrict__ cnt, int* __restrict__ off,
                             int* __restrict__ bsum) {
    __shared__ int s[256];
    int t = threadIdx.x;
    int i = blockIdx.x * 256 + t;
    int v = (i < N_NODES) ? cnt[i] : 0;
    s[t] = v;
    __syncthreads();
#pragma unroll
    for (int o = 1; o < 256; o <<= 1) {
        int x = (t >= o) ? s[t - o] : 0;
        __syncthreads();
        s[t] += x;
        __syncthreads();
    }
    if (i < N_NODES) off[i] = s[t] - v;
    if (t == 255) bsum[blockIdx.x] = s[255];
}
__global__ void scan2_kernel(int* __restrict__ bsum) {
    __shared__ int s[256];
    int t = threadIdx.x;
    int v = (t < SCAN_BLOCKS) ? bsum[t] : 0;
    s[t] = v;
    __syncthreads();
#pragma unroll
    for (int o = 1; o < 256; o <<= 1) {
        int x = (t >= o) ? s[t - o] : 0;
        __syncthreads();
        s[t] += x;
        __syncthreads();
    }
    if (t < SCAN_BLOCKS) bsum[t] = s[t] - v;
}
__global__ void scan3_kernel(int* __restrict__ off, const int* __restrict__ bsum,
                             int* __restrict__ pos) {
    int i = blockIdx.x * blockDim.x + threadIdx.x;
    if (i < N_NODES) {
        int o = off[i] + bsum[i >> 8];
        off[i] = o;
        pos[i] = o;
    }
    if (i == 0) off[N_NODES] = N_EDGES;
}
__global__ void scatter_kernel(const int* __restrict__ ei, const float* __restrict__ dist,
                               int* __restrict__ pos, int* __restrict__ jt,
                               float* __restrict__ cs) {
    int e = blockIdx.x * blockDim.x + threadIdx.x;
    if (e >= N_EDGES) return;
    int j = ei[e];
    int i = ei[N_EDGES + e];
    float d = dist[e];
    int tb = (int)d;
    if (tb > NBINS - 1) tb = NBINS - 1;
    float C = 0.5f * cosf(d * (PI_F / CUTOFF)) + 0.5f;
    int p = atomicAdd(&pos[i], 1);
    jt[p] = j | (tb << 27);
    cs[p] = C;
}

// ---------------- launch ----------------
extern "C" void kernel_launch(void* const* d_in, const int* in_sizes, int n_in,
                              void* d_out, int out_size) {
    const float* z        = (const float*)d_in[0];
    const float* dist     = (const float*)d_in[1];
    const int*   ei       = (const int*)d_in[2];
    const float* init_w   = (const float*)d_in[3];
    const float* init_b   = (const float*)d_in[4];
    const float* e_lin_w[2] = {(const float*)d_in[5],  (const float*)d_in[14]};
    const float* e_m0_w[2]  = {(const float*)d_in[6],  (const float*)d_in[15]};
    const float* e_m0_b[2]  = {(const float*)d_in[7],  (const float*)d_in[16]};
    const float* e_m2_w[2]  = {(const float*)d_in[8],  (const float*)d_in[17]};
    const float* e_m2_b[2]  = {(const float*)d_in[9],  (const float*)d_in[18]};
    const float* v_l1_w[2]  = {(const float*)d_in[10], (const float*)d_in[19]};
    const float* v_l1_b[2]  = {(const float*)d_in[11], (const float*)d_in[20]};
    const float* v_l2_w[2]  = {(const float*)d_in[12], (const float*)d_in[21]};
    const float* v_l2_b[2]  = {(const float*)d_in[13], (const float*)d_in[22]};
    const float* u_l1_w   = (const float*)d_in[23];
    const float* u_l1_b   = (const float*)d_in[24];
    const float* u_l2_w   = (const float*)d_in[25];
    const float* u_l2_b   = (const float*)d_in[26];
    float* out = (float*)d_out;

    float *v, *vlin, *vlin2, *wtab, *cs;
    uint32_t* wpk;
    int *cnt, *off, *pos, *bsum, *jt;
    cudaGetSymbolAddress((void**)&v,     g_v);
    cudaGetSymbolAddress((void**)&vlin,  g_vlin);
    cudaGetSymbolAddress((void**)&vlin2, g_vlin2);
    cudaGetSymbolAddress((void**)&wtab,  g_wtab);
    cudaGetSymbolAddress((void**)&wpk,   g_wpk);
    cudaGetSymbolAddress((void**)&cnt,   g_cnt);
    cudaGetSymbolAddress((void**)&off,   g_off);
    cudaGetSymbolAddress((void**)&pos,   g_pos);
    cudaGetSymbolAddress((void**)&bsum,  g_bsum);
    cudaGetSymbolAddress((void**)&jt,    g_jt);
    cudaGetSymbolAddress((void**)&cs,    g_cs);

    cudaFuncSetAttribute((const void*)gemm0_fused,
                         cudaFuncAttributeMaxDynamicSharedMemorySize, TCG_SMEM);
    cudaFuncSetAttribute((const void*)mlp_fused,
                         cudaFuncAttributeMaxDynamicSharedMemorySize, TCG_SMEM);
    cudaFuncSetAttribute((const void*)mlp_readout_fused,
                         cudaFuncAttributeMaxDynamicSharedMemorySize, TCG_SMEM);

    const int egrid = (N_EDGES + 255) / 256;
    const int ngrid = (N_NODES + 255) / 256;
    const uint32_t* wm[7];  // 0:e_lin0 1:l1_0 2:l2_0 3:e_lin1 4:l1_1 5:l2_1 6:u1
    for (int i = 0; i < 7; i++) wm[i] = wpk + (size_t)i * WIMG_U32;

    table_kernel<<<2 * NBINS, H>>>(e_m0_w[0], e_m0_b[0], e_m2_w[0], e_m2_b[0],      // 0
                                   e_m0_w[1], e_m0_b[1], e_m2_w[1], e_m2_b[1], wtab);
    {
        dim3 wg(32, 7);
        wsplit_kernel<<<wg, 256>>>(e_lin_w[0], v_l1_w[0], v_l2_w[0],                 // 1
                                   e_lin_w[1], v_l1_w[1], v_l2_w[1], u_l1_w, wpk);
    }
    zero_cnt_kernel<<<ngrid, 256>>>(cnt);                                            // 2
    gemm0_fused<<<N_TILES, 512, TCG_SMEM>>>(z, init_w, init_b, wm[0],                // 3 <- profiled
                                            v, vlin, N_NODES);
    hist_kernel<<<egrid, 256>>>(ei, cnt);                                            // 4
    scan1_kernel<<<SCAN_BLOCKS, 256>>>(cnt, off, bsum);                              // 5
    scan2_kernel<<<1, 256>>>(bsum);                                                  // 6
    scan3_kernel<<<SCAN_BLOCKS, 256>>>(off, bsum, pos);                              // 7
    scatter_kernel<<<egrid, 256>>>(ei, dist, pos, jt, cs);                           // 8

    // layer 0: gather(vlin) + l1 -> ssp -> l2 (+v) -> vlin2 = v @ e_lin1
    mlp_fused<<<N_TILES, 512, TCG_SMEM>>>(off, jt, cs, wtab, vlin,                   // 9
                                          wm[1], v_l1_b[0], wm[2], v_l2_b[0],
                                          v, wm[3], vlin2, N_NODES);
    // layer 1 + readout: gather(vlin2) + l1 -> ssp -> l2 (+v) -> u1 -> ssp -> out
    mlp_readout_fused<<<N_TILES, 512, TCG_SMEM>>>(off, jt, cs, wtab + NBINS * H,     // 10
                                                  vlin2, wm[4], v_l1_b[1],
                                                  wm[5], v_l2_b[1], v,
                                                  wm[6], u_l1_b, u_l2_w, u_l2_b,
                                                  out, N_NODES);
}

// round 17
// speedup vs baseline: 1.0827x; 1.0147x over previous
#include <cuda_runtime.h>
#include <cuda_bf16.h>
#include <mma.h>
#include <math.h>
#include <stdint.h>

using namespace nvcuda;

#define N_NODES 50000
#define N_EDGES 800000
#define H 128
#define G_RBF 50
#define NBINS 7
#define CUTOFF 6.0f
#define SSP_SHIFT 0.6931471805599453f
#define PI_F 3.14159265358979323846f

#define SCAN_BLOCKS ((N_NODES + 255) / 256)   // 196
#define TILE_M 64
#define N_TILES ((N_NODES + TILE_M - 1) / TILE_M)   // 782
#define WL 136            // bf16 leading dim (128 + 8 pad)
#define OL 132            // f32 output leading dim (128 + 4 pad)
#define WIMG_U32 17408    // per-matrix packed image: hi(8704 u32) + lo(8704 u32)

// smem layout (bytes)
#define SM_AHI 0
#define SM_ALO (TILE_M * WL * 2)                 // 17408
#define SM_BHI (2 * TILE_M * WL * 2)             // 34816
#define SM_BLO (SM_BHI + H * WL * 2)
#define TCG_SMEM (SM_BHI + 2 * H * WL * 2)       // 104448

// ---------------- scratch ----------------
__device__ float  g_v[N_NODES * H];
__device__ float  g_vlin[N_NODES * H];    // layer-0 edge features
__device__ float  g_vlin2[N_NODES * H];   // layer-1 edge features
__device__ float  g_wtab[2 * NBINS * H];
__device__ uint32_t g_wpk[7 * WIMG_U32];
__device__ int   g_cnt[N_NODES];
__device__ int   g_off[N_NODES + 1];
__device__ int   g_pos[N_NODES];
__device__ int   g_bsum[SCAN_BLOCKS];
__device__ int   g_jt[N_EDGES];
__device__ float g_cs[N_EDGES];

__device__ __forceinline__ float sspf(float x) {
    return fmaxf(x, 0.0f) + log1pf(expf(-fabsf(x))) - SSP_SHIFT;
}

__device__ __forceinline__ uint32_t pack_bf16x2(float x0, float x1) {
    __nv_bfloat16 h0 = __float2bfloat16_rn(x0);
    __nv_bfloat16 h1 = __float2bfloat16_rn(x1);
    return (uint32_t)__bfloat16_as_ushort(h0) |
           ((uint32_t)__bfloat16_as_ushort(h1) << 16);
}

// ---------------- W pre-split ----------------
__global__ void wsplit_kernel(const float* __restrict__ w0, const float* __restrict__ w1,
                              const float* __restrict__ w2, const float* __restrict__ w3,
                              const float* __restrict__ w4, const float* __restrict__ w5,
                              const float* __restrict__ w6, uint32_t* __restrict__ wpk) {
    const float* ws[7] = {w0, w1, w2, w3, w4, w5, w6};
    int m = blockIdx.y;
    const float* W = ws[m];
    int t = blockIdx.x * 256 + threadIdx.x;
    if (t >= 8192) return;
    int n = t & 127;
    int kp = t >> 7;
    float x0 = W[(2 * kp) * H + n];
    float x1 = W[(2 * kp + 1) * H + n];
    float h0 = __bfloat162float(__float2bfloat16_rn(x0));
    float h1 = __bfloat162float(__float2bfloat16_rn(x1));
    uint32_t* base = wpk + (size_t)m * WIMG_U32;
    base[(n * WL + 2 * kp) >> 1]          = pack_bf16x2(x0, x1);
    base[8704 + ((n * WL + 2 * kp) >> 1)] = pack_bf16x2(x0 - h0, x1 - h1);
}

// ================= shared building blocks =================
__device__ __forceinline__ void stage_B(char* sm, const uint32_t* wpk, int tid) {
    const float4* src = (const float4*)wpk;
    float4* dst = (float4*)(sm + SM_BHI);
    for (int i = tid; i < (2 * H * WL * 2) / 16; i += 512) dst[i] = src[i];
}

__device__ __forceinline__ void store_A4(char* sm, int node, int c, float4 a) {
    float hx = __bfloat162float(__float2bfloat16_rn(a.x));
    float hy = __bfloat162float(__float2bfloat16_rn(a.y));
    float hz = __bfloat162float(__float2bfloat16_rn(a.z));
    float hw = __bfloat162float(__float2bfloat16_rn(a.w));
    uint32_t boff = 2 * (node * WL + 4 * c);
    *(uint2*)(sm + SM_AHI + boff) = make_uint2(pack_bf16x2(a.x, a.y), pack_bf16x2(a.z, a.w));
    *(uint2*)(sm + SM_ALO + boff) = make_uint2(pack_bf16x2(a.x - hx, a.y - hy),
                                               pack_bf16x2(a.z - hz, a.w - hw));
}

__device__ __forceinline__ void mma_set(const char* sm, int wid,
        wmma::fragment<wmma::accumulator, 16, 16, 16, float>* acc) {
    int wrow = wid & 3, wcol = wid >> 2;
    const __nv_bfloat16* Ahi = (const __nv_bfloat16*)(sm + SM_AHI) + wrow * 16 * WL;
    const __nv_bfloat16* Alo = (const __nv_bfloat16*)(sm + SM_ALO) + wrow * 16 * WL;
    const __nv_bfloat16* Bhi = (const __nv_bfloat16*)(sm + SM_BHI);
    const __nv_bfloat16* Blo = (const __nv_bfloat16*)(sm + SM_BLO);
#pragma unroll
    for (int t = 0; t < 2; t++) wmma::fill_fragment(acc[t], 0.0f);
#pragma unroll
    for (int ks = 0; ks < 8; ks++) {
        wmma::fragment<wmma::matrix_a, 16, 16, 16, __nv_bfloat16, wmma::row_major> ah, al;
        wmma::load_matrix_sync(ah, Ahi + ks * 16, WL);
        wmma::load_matrix_sync(al, Alo + ks * 16, WL);
#pragma unroll
        for (int t = 0; t < 2; t++) {
            int ncol = wcol * 32 + t * 16;
            wmma::fragment<wmma::matrix_b, 16, 16, 16, __nv_bfloat16, wmma::col_major> bh, bl;
            wmma::load_matrix_sync(bh, Bhi + ncol * WL + ks * 16, WL);
            wmma::load_matrix_sync(bl, Blo + ncol * WL + ks * 16, WL);
            wmma::mma_sync(acc[t], ah, bh, acc[t]);
            wmma::mma_sync(acc[t], ah, bl, acc[t]);
            wmma::mma_sync(acc[t], al, bh, acc[t]);
        }
    }
}

__device__ __forceinline__ void store_set(char* sm, int wid,
        wmma::fragment<wmma::accumulator, 16, 16, 16, float>* acc) {
    int wrow = wid & 3, wcol = wid >> 2;
    float* osm = (float*)(sm + SM_AHI);
#pragma unroll
    for (int t = 0; t < 2; t++)
        wmma::store_matrix_sync(osm + wrow * 16 * OL + wcol * 32 + t * 16,
                                acc[t], OL, wmma::mem_row_major);
}

// in-kernel gather of one node's aggregated edge features (warp-collective)
__device__ __forceinline__ float4 gather_node(const float4* __restrict__ vlin4,
                                              const int* __restrict__ off,
                                              const int* __restrict__ jt,
                                              const float* __restrict__ cs,
                                              const float4* wsg,
                                              int gnode, int lane) {
    float4 acc = make_float4(0.f, 0.f, 0.f, 0.f);
    int s = off[gnode], e = off[gnode + 1];
    for (int base = s; base < e; base += 32) {
        int m = min(32, e - base);
        int mj = (lane < m) ? jt[base + lane] : 0;
        float mc = (lane < m) ? cs[base + lane] : 0.f;
        int t = 0;
        for (; t + 4 <= m; t += 4) {
            int jv0 = __shfl_sync(0xffffffffu, mj, t);
            int jv1 = __shfl_sync(0xffffffffu, mj, t + 1);
            int jv2 = __shfl_sync(0xffffffffu, mj, t + 2);
            int jv3 = __shfl_sync(0xffffffffu, mj, t + 3);
            float c0 = __shfl_sync(0xffffffffu, mc, t);
            float c1 = __shfl_sync(0xffffffffu, mc, t + 1);
            float c2 = __shfl_sync(0xffffffffu, mc, t + 2);
            float c3 = __shfl_sync(0xffffffffu, mc, t + 3);
            float4 x0 = __ldg(vlin4 + (size_t)(jv0 & 0x07FFFFFF) * 32 + lane);
            float4 x1 = __ldg(vlin4 + (size_t)(jv1 & 0x07FFFFFF) * 32 + lane);
            float4 x2 = __ldg(vlin4 + (size_t)(jv2 & 0x07FFFFFF) * 32 + lane);
            float4 x3 = __ldg(vlin4 + (size_t)(jv3 & 0x07FFFFFF) * 32 + lane);
            float4 w0 = wsg[(jv0 >> 27) * 32 + lane];
            float4 w1 = wsg[(jv1 >> 27) * 32 + lane];
            float4 w2 = wsg[(jv2 >> 27) * 32 + lane];
            float4 w3 = wsg[(jv3 >> 27) * 32 + lane];
            acc.x += x0.x * w0.x * c0; acc.y += x0.y * w0.y * c0;
            acc.z += x0.z * w0.z * c0; acc.w += x0.w * w0.w * c0;
            acc.x += x1.x * w1.x * c1; acc.y += x1.y * w1.y * c1;
            acc.z += x1.z * w1.z * c1; acc.w += x1.w * w1.w * c1;
            acc.x += x2.x * w2.x * c2; acc.y += x2.y * w2.y * c2;
            acc.z += x2.z * w2.z * c2; acc.w += x2.w * w2.w * c2;
            acc.x += x3.x * w3.x * c3; acc.y += x3.y * w3.y * c3;
            acc.z += x3.z * w3.z * c3; acc.w += x3.w * w3.w * c3;
        }
        for (; t < m; t++) {
            int jv = __shfl_sync(0xffffffffu, mj, t);
            float c = __shfl_sync(0xffffffffu, mc, t);
            float4 x = __ldg(vlin4 + (size_t)(jv & 0x07FFFFFF) * 32 + lane);
            float4 w = wsg[(jv >> 27) * 32 + lane];
            acc.x += x.x * w.x * c;
            acc.y += x.y * w.y * c;
            acc.z += x.z * w.z * c;
            acc.w += x.w * w.w * c;
        }
    }
    return acc;
}

// ---------------- gemm0_fused: v = z@iw+ib (written), vlin = v @ e_lin0 ----------------
__global__ void __launch_bounds__(512, 2) gemm0_fused(const float* __restrict__ z,
                                                      const float* __restrict__ iw,
                                                      const float* __restrict__ ib,
                                                      const uint32_t* __restrict__ wpk,
                                                      float* __restrict__ vout,
                                                      float* __restrict__ vlin, int n) {
    extern __shared__ char sm[];
    int tid = threadIdx.x;
    int nb = blockIdx.x * TILE_M;

    stage_B(sm, wpk, tid);
    for (int idx = tid; idx < TILE_M * 32; idx += 512) {
        int node = idx >> 5, c = idx & 31;
        int gn = nb + node;
        float4 val = make_float4(0.f, 0.f, 0.f, 0.f);
        if (gn < n) {
            float z0 = __ldg(z + gn * 3), z1 = __ldg(z + gn * 3 + 1), z2 = __ldg(z + gn * 3 + 2);
            float4 b  = __ldg((const float4*)ib + c);
            float4 w0 = __ldg((const float4*)iw + c);
            float4 w1 = __ldg((const float4*)iw + 32 + c);
            float4 w2 = __ldg((const float4*)iw + 64 + c);
            val.x = b.x + z0 * w0.x + z1 * w1.x + z2 * w2.x;
            val.y = b.y + z0 * w0.y + z1 * w1.y + z2 * w2.y;
            val.z = b.z + z0 * w0.z + z1 * w1.z + z2 * w2.z;
            val.w = b.w + z0 * w0.w + z1 * w1.w + z2 * w2.w;
            ((float4*)vout)[(size_t)gn * 32 + c] = val;
        }
        store_A4(sm, node, c, val);
    }
    __syncthreads();

    int wid = tid >> 5;
    wmma::fragment<wmma::accumulator, 16, 16, 16, float> acc[2];
    mma_set(sm, wid, acc);
    __syncthreads();
    store_set(sm, wid, acc);
    __syncthreads();

    int node = tid >> 3, cb = (tid & 7) * 16;
    int gn = nb + node;
    if (gn < n) {
        const float* ip = (const float*)(sm + SM_AHI) + node * OL + cb;
        float4* op = (float4*)(vlin + (size_t)gn * H + cb);
#pragma unroll
        for (int i = 0; i < 4; i++)
            op[i] = make_float4(ip[4 * i], ip[4 * i + 1], ip[4 * i + 2], ip[4 * i + 3]);
    }
}

// ---------------- mlp_fused (layer 0, gather fused) ----------------
__global__ void __launch_bounds__(512, 2) mlp_fused(const int* __restrict__ off,
                                                    const int* __restrict__ jt,
                                                    const float* __restrict__ cs,
                                                    const float* __restrict__ wtab,
                                                    const float* __restrict__ vlin_in,
                                                    const uint32_t* __restrict__ wpk1,
                                                    const float* __restrict__ b1,
                                                    const uint32_t* __restrict__ wpk2,
                                                    const float* __restrict__ b2,
                                                    float* __restrict__ v,
                                                    const uint32_t* __restrict__ wpkL,
                                                    float* __restrict__ vlin_out, int n) {
    extern __shared__ char sm[];
    __shared__ float bs1[H], bs2[H];
    __shared__ float4 wsg[NBINS * 32];
    int tid = threadIdx.x;
    int nb = blockIdx.x * TILE_M;
    if (tid < H) { bs1[tid] = b1[tid]; bs2[tid] = b2[tid]; }
    if (tid < NBINS * 32) wsg[tid] = ((const float4*)wtab)[tid];
    __syncthreads();

    stage_B(sm, wpk1, tid);

    int wid = tid >> 5, lane = tid & 31;
    const float4* vlin4 = (const float4*)vlin_in;
    for (int nn = wid; nn < TILE_M; nn += 16) {
        int gnode = nb + nn;
        float4 a = make_float4(0.f, 0.f, 0.f, 0.f);
        if (gnode < n) a = gather_node(vlin4, off, jt, cs, wsg, gnode, lane);
        store_A4(sm, nn, lane, a);
    }
    __syncthreads();

    int node = tid >> 3, cb = (tid & 7) * 16;
    int gn = nb + node;
    wmma::fragment<wmma::accumulator, 16, 16, 16, float> acc[2];

    // set 1: h = ssp(agg@W1 + b1)
    mma_set(sm, wid, acc);
    __syncthreads();
    store_set(sm, wid, acc);
    __syncthreads();

    float t1[16];
    {
        const float* ip = (const float*)(sm + SM_AHI) + node * OL + cb;
#pragma unroll
        for (int i = 0; i < 16; i++) t1[i] = sspf(ip[i] + bs1[cb + i]);
    }
    __syncthreads();
#pragma unroll
    for (int i = 0; i < 4; i++)
        store_A4(sm, node, (cb >> 2) + i,
                 make_float4(t1[4 * i], t1[4 * i + 1], t1[4 * i + 2], t1[4 * i + 3]));
    stage_B(sm, wpk2, tid);
    __syncthreads();

    // set 2: o = h@W2 + b2 + v   (write v)
    mma_set(sm, wid, acc);
    __syncthreads();
    store_set(sm, wid, acc);
    __syncthreads();

    float o[16];
    {
        const float* ip = (const float*)(sm + SM_AHI) + node * OL + cb;
        if (gn < n) {
            const float* rp = v + (size_t)gn * H + cb;
#pragma unroll
            for (int i = 0; i < 16; i++) o[i] = ip[i] + bs2[cb + i] + rp[i];
            float4* op = (float4*)(v + (size_t)gn * H + cb);
#pragma unroll
            for (int i = 0; i < 4; i++)
                op[i] = make_float4(o[4 * i], o[4 * i + 1], o[4 * i + 2], o[4 * i + 3]);
        } else {
#pragma unroll
            for (int i = 0; i < 16; i++) o[i] = 0.f;
        }
    }
    __syncthreads();
#pragma unroll
    for (int i = 0; i < 4; i++)
        store_A4(sm, node, (cb >> 2) + i,
                 make_float4(o[4 * i], o[4 * i + 1], o[4 * i + 2], o[4 * i + 3]));
    stage_B(sm, wpkL, tid);
    __syncthreads();

    // set 3: vlin_out = v_new @ linW
    mma_set(sm, wid, acc);
    __syncthreads();
    store_set(sm, wid, acc);
    __syncthreads();

    if (gn < n) {
        const float* ip = (const float*)(sm + SM_AHI) + node * OL + cb;
        float4* op = (float4*)(vlin_out + (size_t)gn * H + cb);
#pragma unroll
        for (int i = 0; i < 4; i++)
            op[i] = make_float4(ip[4 * i], ip[4 * i + 1], ip[4 * i + 2], ip[4 * i + 3]);
    }
}

// ---------------- mlp_readout_fused (layer 1 + readout, gather fused) ----------------
__global__ void __launch_bounds__(512, 2) mlp_readout_fused(const int* __restrict__ off,
                                                            const int* __restrict__ jt,
                                                            const float* __restrict__ cs,
                                                            const float* __restrict__ wtab,
                                                            const float* __restrict__ vlin_in,
                                                            const uint32_t* __restrict__ wpk1,
                                                            const float* __restrict__ b1,
                                                            const uint32_t* __restrict__ wpk2,
                                                            const float* __restrict__ b2,
                                                            const float* __restrict__ v,
                                                            const uint32_t* __restrict__ wpkU,
                                                            const float* __restrict__ bu,
                                                            const float* __restrict__ U2,
                                                            const float* __restrict__ b2u,
                                                            float* __restrict__ out, int n) {
    extern __shared__ char sm[];
    __shared__ float bs1[H], bs2[H], bsu[H], ws2[H * 3];
    __shared__ float4 wsg[NBINS * 32];
    int tid = threadIdx.x;
    int nb = blockIdx.x * TILE_M;
    if (tid < H) { bs1[tid] = b1[tid]; bs2[tid] = b2[tid]; bsu[tid] = bu[tid]; }
    for (int idx = tid; idx < H * 3; idx += 512) ws2[idx] = U2[idx];
    if (tid < NBINS * 32) wsg[tid] = ((const float4*)wtab)[tid];
    __syncthreads();

    stage_B(sm, wpk1, tid);

    int wid = tid >> 5, lane = tid & 31;
    const float4* vlin4 = (const float4*)vlin_in;
    for (int nn = wid; nn < TILE_M; nn += 16) {
        int gnode = nb + nn;
        float4 a = make_float4(0.f, 0.f, 0.f, 0.f);
        if (gnode < n) a = gather_node(vlin4, off, jt, cs, wsg, gnode, lane);
        store_A4(sm, nn, lane, a);
    }
    __syncthreads();

    int node = tid >> 3, cb = (tid & 7) * 16;
    int gn = nb + node;
    wmma::fragment<wmma::accumulator, 16, 16, 16, float> acc[2];

    // set 1
    mma_set(sm, wid, acc);
    __syncthreads();
    store_set(sm, wid, acc);
    __syncthreads();

    float t1[16];
    {
        const float* ip = (const float*)(sm + SM_AHI) + node * OL + cb;
#pragma unroll
        for (int i = 0; i < 16; i++) t1[i] = sspf(ip[i] + bs1[cb + i]);
    }
    __syncthreads();
#pragma unroll
    for (int i = 0; i < 4; i++)
        store_A4(sm, node, (cb >> 2) + i,
                 make_float4(t1[4 * i], t1[4 * i + 1], t1[4 * i + 2], t1[4 * i + 3]));
    stage_B(sm, wpk2, tid);
    __syncthreads();

    // set 2: vn = h@W2 + b2 + v   (no global write)
    mma_set(sm, wid, acc);
    __syncthreads();
    store_set(sm, wid, acc);
    __syncthreads();

    float o[16];
    {
        const float* ip = (const float*)(sm + SM_AHI) + node * OL + cb;
        if (gn < n) {
            const float* rp = v + (size_t)gn * H + cb;
#pragma unroll
            for (int i = 0; i < 16; i++) o[i] = ip[i] + bs2[cb + i] + rp[i];
        } else {
#pragma unroll
            for (int i = 0; i < 16; i++) o[i] = 0.f;
        }
    }
    __syncthreads();
#pragma unroll
    for (int i = 0; i < 4; i++)
        store_A4(sm, node, (cb >> 2) + i,
                 make_float4(o[4 * i], o[4 * i + 1], o[4 * i + 2], o[4 * i + 3]));
    stage_B(sm, wpkU, tid);
    __syncthreads();

    // set 3: hu = ssp(vn@U1 + bu); project to 3 and reduce
    mma_set(sm, wid, acc);
    __syncthreads();
    store_set(sm, wid, acc);
    __syncthreads();

    float p0 = 0.f, p1 = 0.f, p2 = 0.f;
    {
        const float* ip = (const float*)(sm + SM_AHI) + node * OL + cb;
#pragma unroll
        for (int i = 0; i < 16; i++) {
            float x = sspf(ip[i] + bsu[cb + i]);
            int col = cb + i;
            p0 += x * ws2[col * 3 + 0];
            p1 += x * ws2[col * 3 + 1];
            p2 += x * ws2[col * 3 + 2];
        }
    }
#pragma unroll
    for (int offs = 4; offs; offs >>= 1) {
        p0 += __shfl_down_sync(0xffffffffu, p0, offs, 8);
        p1 += __shfl_down_sync(0xffffffffu, p1, offs, 8);
        p2 += __shfl_down_sync(0xffffffffu, p2, offs, 8);
    }
    if ((tid & 7) == 0 && gn < n) {
        out[gn * 3 + 0] = p0 + b2u[0];
        out[gn * 3 + 1] = p1 + b2u[1];
        out[gn * 3 + 2] = p2 + b2u[2];
    }
}

// ---------------- filter table ----------------
__global__ void table_kernel(const float* __restrict__ m0w0, const float* __restrict__ m0b0,
                             const float* __restrict__ m2w0, const float* __restrict__ m2b0,
                             const float* __restrict__ m0w1, const float* __restrict__ m0b1,
                             const float* __restrict__ m2w1, const float* __restrict__ m2b1,
                             float* __restrict__ wtab) {
    int l = blockIdx.x / NBINS;
    int t = blockIdx.x % NBINS;
    const float* m0w = l ? m0w1 : m0w0;
    const float* m0b = l ? m0b1 : m0b0;
    const float* m2w = l ? m2w1 : m2w0;
    const float* m2b = l ? m2b1 : m2b0;
    __shared__ float hs[H];
    int h = threadIdx.x;
    const float step = CUTOFF / (float)(G_RBF - 1);
    const float coeff = -0.5f / (step * step);
    float acc = m0b[h];
#pragma unroll 10
    for (int g = 0; g < G_RBF; g++) {
        float dd = (float)t - step * (float)g;
        acc += expf(coeff * dd * dd) * m0w[g * H + h];
    }
    hs[h] = sspf(acc);
    __syncthreads();
    float o = m2b[h];
#pragma unroll 16
    for (int k = 0; k < H; k++) o += hs[k] * m2w[k * H + h];
    wtab[(l * NBINS + t) * H + h] = o;
}

// ---------------- CSR build ----------------
__global__ void zero_cnt_kernel(int* __restrict__ cnt) {
    int i = blockIdx.x * blockDim.x + threadIdx.x;
    if (i < N_NODES) cnt[i] = 0;
}
__global__ void hist_kernel(const int* __restrict__ ei, int* __restrict__ cnt) {
    int e = blockIdx.x * blockDim.x + threadIdx.x;
    if (e < N_EDGES) atomicAdd(&cnt[ei[N_EDGES + e]], 1);
}
__global__ void scan1_kernel(const int* __restrict__ cnt, int* __restrict__ off,
                             int* __restrict__ bsum) {
    __shared__ int s[256];
    int t = threadIdx.x;
    int i = blockIdx.x * 256 + t;
    int v = (i < N_NODES) ? cnt[i] : 0;
    s[t] = v;
    __syncthreads();
#pragma unroll
    for (int o = 1; o < 256; o <<= 1) {
        int x = (t >= o) ? s[t - o] : 0;
        __syncthreads();
        s[t] += x;
        __syncthreads();
    }
    if (i < N_NODES) off[i] = s[t] - v;
    if (t == 255) bsum[blockIdx.x] = s[255];
}
__global__ void scan2_kernel(int* __restrict__ bsum) {
    __shared__ int s[256];
    int t = threadIdx.x;
    int v = (t < SCAN_BLOCKS) ? bsum[t] : 0;
    s[t] = v;
    __syncthreads();
#pragma unroll
    for (int o = 1; o < 256; o <<= 1) {
        int x = (t >= o) ? s[t - o] : 0;
        __syncthreads();
        s[t] += x;
        __syncthreads();
    }
    if (t < SCAN_BLOCKS) bsum[t] = s[t] - v;
}
__global__ void scan3_kernel(int* __restrict__ off, const int* __restrict__ bsum,
                             int* __restrict__ pos) {
    int i = blockIdx.x * blockDim.x + threadIdx.x;
    if (i < N_NODES) {
        int o = off[i] + bsum[i >> 8];
        off[i] = o;
        pos[i] = o;
    }
    if (i == 0) off[N_NODES] = N_EDGES;
}
__global__ void scatter_kernel(const int* __restrict__ ei, const float* __restrict__ dist,
                               int* __restrict__ pos, int* __restrict__ jt,
                               float* __restrict__ cs) {
    int e = blockIdx.x * blockDim.x + threadIdx.x;
    if (e >= N_EDGES) return;
    int j = ei[e];
    int i = ei[N_EDGES + e];
    float d = dist[e];
    int tb = (int)d;
    if (tb > NBINS - 1) tb = NBINS - 1;
    float C = 0.5f * cosf(d * (PI_F / CUTOFF)) + 0.5f;
    int p = atomicAdd(&pos[i], 1);
    jt[p] = j | (tb << 27);
    cs[p] = C;
}

// ---------------- launch ----------------
extern "C" void kernel_launch(void* const* d_in, const int* in_sizes, int n_in,
                              void* d_out, int out_size) {
    const float* z        = (const float*)d_in[0];
    const float* dist     = (const float*)d_in[1];
    const int*   ei       = (const int*)d_in[2];
    const float* init_w   = (const float*)d_in[3];
    const float* init_b   = (const float*)d_in[4];
    const float* e_lin_w[2] = {(const float*)d_in[5],  (const float*)d_in[14]};
    const float* e_m0_w[2]  = {(const float*)d_in[6],  (const float*)d_in[15]};
    const float* e_m0_b[2]  = {(const float*)d_in[7],  (const float*)d_in[16]};
    const float* e_m2_w[2]  = {(const float*)d_in[8],  (const float*)d_in[17]};
    const float* e_m2_b[2]  = {(const float*)d_in[9],  (const float*)d_in[18]};
    const float* v_l1_w[2]  = {(const float*)d_in[10], (const float*)d_in[19]};
    const float* v_l1_b[2]  = {(const float*)d_in[11], (const float*)d_in[20]};
    const float* v_l2_w[2]  = {(const float*)d_in[12], (const float*)d_in[21]};
    const float* v_l2_b[2]  = {(const float*)d_in[13], (const float*)d_in[22]};
    const float* u_l1_w   = (const float*)d_in[23];
    const float* u_l1_b   = (const float*)d_in[24];
    const float* u_l2_w   = (const float*)d_in[25];
    const float* u_l2_b   = (const float*)d_in[26];
    float* out = (float*)d_out;

    float *v, *vlin, *vlin2, *wtab, *cs;
    uint32_t* wpk;
    int *cnt, *off, *pos, *bsum, *jt;
    cudaGetSymbolAddress((void**)&v,     g_v);
    cudaGetSymbolAddress((void**)&vlin,  g_vlin);
    cudaGetSymbolAddress((void**)&vlin2, g_vlin2);
    cudaGetSymbolAddress((void**)&wtab,  g_wtab);
    cudaGetSymbolAddress((void**)&wpk,   g_wpk);
    cudaGetSymbolAddress((void**)&cnt,   g_cnt);
    cudaGetSymbolAddress((void**)&off,   g_off);
    cudaGetSymbolAddress((void**)&pos,   g_pos);
    cudaGetSymbolAddress((void**)&bsum,  g_bsum);
    cudaGetSymbolAddress((void**)&jt,    g_jt);
    cudaGetSymbolAddress((void**)&cs,    g_cs);

    cudaFuncSetAttribute((const void*)gemm0_fused,
                         cudaFuncAttributeMaxDynamicSharedMemorySize, TCG_SMEM);
    cudaFuncSetAttribute((const void*)mlp_fused,
                         cudaFuncAttributeMaxDynamicSharedMemorySize, TCG_SMEM);
    cudaFuncSetAttribute((const void*)mlp_readout_fused,
                         cudaFuncAttributeMaxDynamicSharedMemorySize, TCG_SMEM);

    // side stream + events (created once on first, uncaptured, call)
    static cudaStream_t s2 = nullptr;
    static cudaEvent_t evFork = nullptr, evJoin = nullptr;
    if (!s2) {
        cudaStreamCreateWithFlags(&s2, cudaStreamNonBlocking);
        cudaEventCreateWithFlags(&evFork, cudaEventDisableTiming);
        cudaEventCreateWithFlags(&evJoin, cudaEventDisableTiming);
    }
    cudaStream_t s0 = 0;   // harness capture stream

    const int egrid = (N_EDGES + 255) / 256;
    const int ngrid = (N_NODES + 255) / 256;
    const uint32_t* wm[7];  // 0:e_lin0 1:l1_0 2:l2_0 3:e_lin1 4:l1_1 5:l2_1 6:u1
    for (int i = 0; i < 7; i++) wm[i] = wpk + (size_t)i * WIMG_U32;

    // fork: CSR build + filter table on side stream, concurrent with wsplit+gemm0
    cudaEventRecord(evFork, s0);
    cudaStreamWaitEvent(s2, evFork, 0);

    // --- side stream: independent of v/wpk ---
    zero_cnt_kernel<<<ngrid, 256, 0, s2>>>(cnt);
    hist_kernel<<<egrid, 256, 0, s2>>>(ei, cnt);
    scan1_kernel<<<SCAN_BLOCKS, 256, 0, s2>>>(cnt, off, bsum);
    scan2_kernel<<<1, 256, 0, s2>>>(bsum);
    scan3_kernel<<<SCAN_BLOCKS, 256, 0, s2>>>(off, bsum, pos);
    scatter_kernel<<<egrid, 256, 0, s2>>>(ei, dist, pos, jt, cs);
    table_kernel<<<2 * NBINS, H, 0, s2>>>(e_m0_w[0], e_m0_b[0], e_m2_w[0], e_m2_b[0],
                                          e_m0_w[1], e_m0_b[1], e_m2_w[1], e_m2_b[1], wtab);

    // --- main stream: weight prep + node init GEMM ---
    {
        dim3 wg(32, 7);
        wsplit_kernel<<<wg, 256, 0, s0>>>(e_lin_w[0], v_l1_w[0], v_l2_w[0],
                                          e_lin_w[1], v_l1_w[1], v_l2_w[1], u_l1_w, wpk);
    }
    gemm0_fused<<<N_TILES, 512, TCG_SMEM, s0>>>(z, init_w, init_b, wm[0],
                                                v, vlin, N_NODES);

    // join
    cudaEventRecord(evJoin, s2);
    cudaStreamWaitEvent(s0, evJoin, 0);

    // layer 0: gather(vlin) + l1 -> ssp -> l2 (+v) -> vlin2 = v @ e_lin1
    mlp_fused<<<N_TILES, 512, TCG_SMEM, s0>>>(off, jt, cs, wtab, vlin,
                                              wm[1], v_l1_b[0], wm[2], v_l2_b[0],
                                              v, wm[3], vlin2, N_NODES);
    // layer 1 + readout: gather(vlin2) + l1 -> ssp -> l2 (+v) -> u1 -> ssp -> out
    mlp_readout_fused<<<N_TILES, 512, TCG_SMEM, s0>>>(off, jt, cs, wtab + NBINS * H,
                                                      vlin2, wm[4], v_l1_b[1],
                                                      wm[5], v_l2_b[1], v,
                                                      wm[6], u_l1_b, u_l2_w, u_l2_b,
                                                      out, N_NODES);
}